// round 9
// baseline (speedup 1.0000x reference)
#include <cuda_runtime.h>
#include <stdint.h>

// out[b,h,w,:] = graph[b, slic[b,h,w]-1, :]
//   graph: [B=4, S=256, C=128] fp32  -> 128 KiB/batch, L1D-resident (no smem)
//   slic:  [B=4, 512, 512] int32     -> streamed (evict-first)
//   out:   [B, 512, 512, 128] fp32   -> 512 MiB evict-first streaming stores
//
// 8 pixels per warp-step: 2 uniform int4 id-loads, 8 independent L1-hit
// gathers, then a 4 KiB contiguous burst of 8 STG.128.cs per warp.

static constexpr int B  = 4;
static constexpr int S  = 256;
static constexpr int C  = 128;
static constexpr int HW = 512 * 512;                  // 2^18
static constexpr int NPIX = B * HW;                   // 1,048,576

static constexpr int THREADS       = 256;             // 8 warps
static constexpr int PIX_PER_WARP  = 64;
static constexpr int PIX_PER_BLOCK = 8 * PIX_PER_WARP;        // 512
static constexpr int BLOCKS        = NPIX / PIX_PER_BLOCK;    // 2048

__global__ __launch_bounds__(THREADS)
void convert2image_cs8_kernel(const float* __restrict__ graph,
                              const int*   __restrict__ slic,
                              float*       __restrict__ out) {
    const int warp = threadIdx.x >> 5;
    const int lane = threadIdx.x & 31;

    // This warp's 64 contiguous pixels (512 | 2^18 -> no batch straddle).
    const int pix0 = blockIdx.x * PIX_PER_BLOCK + warp * PIX_PER_WARP;
    const int b    = pix0 >> 18;

    const float4* tab  = reinterpret_cast<const float4*>(graph) + (size_t)b * (S * C / 4); // [S][32]
    const int4*   sid4 = reinterpret_cast<const int4*>(slic) + (pix0 >> 2);                // 16 int4
    float4*       dst  = reinterpret_cast<float4*>(out) + (size_t)pix0 * 32 + lane;

    #pragma unroll
    for (int step = 0; step < 8; step++) {            // 8 pixels per step
        // 8 segment ids via two uniform evict-first 16 B loads (independent).
        const int4 ia = __ldcs(&sid4[step * 2 + 0]);
        const int4 ib = __ldcs(&sid4[step * 2 + 1]);

        // 8 independent L1-hit gathers (table resident in 228 KiB L1D).
        const float4 v0 = __ldg(&tab[(ia.x - 1) * 32 + lane]);
        const float4 v1 = __ldg(&tab[(ia.y - 1) * 32 + lane]);
        const float4 v2 = __ldg(&tab[(ia.z - 1) * 32 + lane]);
        const float4 v3 = __ldg(&tab[(ia.w - 1) * 32 + lane]);
        const float4 v4 = __ldg(&tab[(ib.x - 1) * 32 + lane]);
        const float4 v5 = __ldg(&tab[(ib.y - 1) * 32 + lane]);
        const float4 v6 = __ldg(&tab[(ib.z - 1) * 32 + lane]);
        const float4 v7 = __ldg(&tab[(ib.w - 1) * 32 + lane]);

        // 4 KiB contiguous evict-first store burst (8 x 512 B).
        float4* d = dst + step * 256;
        __stcs(&d[  0], v0);
        __stcs(&d[ 32], v1);
        __stcs(&d[ 64], v2);
        __stcs(&d[ 96], v3);
        __stcs(&d[128], v4);
        __stcs(&d[160], v5);
        __stcs(&d[192], v6);
        __stcs(&d[224], v7);
    }
}

extern "C" void kernel_launch(void* const* d_in, const int* in_sizes, int n_in,
                              void* d_out, int out_size) {
    const float* graph = (const float*)d_in[0];
    const int*   slic  = (const int*)d_in[1];
    float*       out   = (float*)d_out;

    convert2image_cs8_kernel<<<BLOCKS, THREADS>>>(graph, slic, out);
}

// round 11
// speedup vs baseline: 1.1042x; 1.1042x over previous
#include <cuda_runtime.h>
#include <stdint.h>

// out[b,h,w,:] = graph[b, slic[b,h,w]-1, :]
//   graph: [B=4, S=256, C=128] fp32  -> 128 KiB/batch, L1D-resident (no smem)
//   slic:  [B=4, 512, 512] int32     -> streamed (evict-first), prefetched 1 step
//   out:   [B, 512, 512, 128] fp32   -> 512 MiB evict-first streaming stores
//
// Identical to the 84.2us winner (4 px/step, 2 KiB bursts, __stcs) plus a
// one-step index prefetch so no store burst waits on a DRAM-latency id load.

static constexpr int B  = 4;
static constexpr int S  = 256;
static constexpr int C  = 128;
static constexpr int HW = 512 * 512;                  // 2^18
static constexpr int NPIX = B * HW;                   // 1,048,576

static constexpr int THREADS       = 256;             // 8 warps
static constexpr int PIX_PER_WARP  = 32;
static constexpr int PIX_PER_BLOCK = 8 * PIX_PER_WARP;        // 256
static constexpr int BLOCKS        = NPIX / PIX_PER_BLOCK;    // 4096

__global__ __launch_bounds__(THREADS)
void convert2image_cs_pf_kernel(const float* __restrict__ graph,
                                const int*   __restrict__ slic,
                                float*       __restrict__ out) {
    const int warp = threadIdx.x >> 5;
    const int lane = threadIdx.x & 31;

    // This warp's 32 contiguous pixels (256 | 2^18 -> no batch straddle).
    const int pix0 = blockIdx.x * PIX_PER_BLOCK + warp * PIX_PER_WARP;
    const int b    = pix0 >> 18;

    const float4* tab  = reinterpret_cast<const float4*>(graph) + (size_t)b * (S * C / 4); // [S][32]
    const int4*   sid4 = reinterpret_cast<const int4*>(slic) + (pix0 >> 2);                // 8 int4
    float4*       dst  = reinterpret_cast<float4*>(out) + (size_t)pix0 * 32 + lane;

    // Prefetch step 0's ids.
    int4 iv = __ldcs(&sid4[0]);

    #pragma unroll
    for (int step = 0; step < 8; step++) {            // 4 pixels per step
        // Prefetch next step's ids before consuming the current ones, so the
        // id-load DRAM latency overlaps this step's gathers + store burst.
        int4 nv;
        if (step < 7) nv = __ldcs(&sid4[step + 1]);

        // 4 independent L1-hit gathers (table resident in 228 KiB L1D).
        const float4 v0 = __ldg(&tab[(iv.x - 1) * 32 + lane]);
        const float4 v1 = __ldg(&tab[(iv.y - 1) * 32 + lane]);
        const float4 v2 = __ldg(&tab[(iv.z - 1) * 32 + lane]);
        const float4 v3 = __ldg(&tab[(iv.w - 1) * 32 + lane]);

        // 2 KiB contiguous evict-first store burst (4 x 512 B).
        float4* d = dst + step * 128;
        __stcs(&d[ 0], v0);
        __stcs(&d[32], v1);
        __stcs(&d[64], v2);
        __stcs(&d[96], v3);

        iv = nv;
    }
}

extern "C" void kernel_launch(void* const* d_in, const int* in_sizes, int n_in,
                              void* d_out, int out_size) {
    const float* graph = (const float*)d_in[0];
    const int*   slic  = (const int*)d_in[1];
    float*       out   = (float*)d_out;

    convert2image_cs_pf_kernel<<<BLOCKS, THREADS>>>(graph, slic, out);
}